// round 7
// baseline (speedup 1.0000x reference)
#include <cuda_runtime.h>

#define N_NODES 50000
#define E_PER   300000
#define ETOT    900000
#define HID     64

// ---------------- scratch (__device__ globals; no allocations) ----------------
__device__ int   g_counts[N_NODES];
__device__ int   g_pos[N_NODES];
__device__ int   g_rowptr[N_NODES + 1];
__device__ int   g_ekey[ETOT];     // (col << 2) | etype
__device__ float g_ew[ETOT];       // edge value
__device__ float g_X0[2 * N_NODES * HID];   // per-channel H after GEMM (kept as X0)
__device__ float g_A [2 * N_NODES * HID];   // ping
__device__ float g_B [2 * N_NODES * HID];   // pong
__device__ float g_Xmid[N_NODES * HID];     // output of block 0

static const unsigned FULL = 0xffffffffu;

// ---------------- CSR build ----------------
__global__ void zero_counts_kernel() {
    int i = blockIdx.x * blockDim.x + threadIdx.x;
    if (i < N_NODES) g_counts[i] = 0;
}

__global__ void hist_kernel(const int* __restrict__ e0, const int* __restrict__ e1,
                            const int* __restrict__ e2) {
    int i = blockIdx.x * blockDim.x + threadIdx.x;
    if (i < E_PER) {
        atomicAdd(&g_counts[e0[i]], 1);
        atomicAdd(&g_counts[e1[i]], 1);
        atomicAdd(&g_counts[e2[i]], 1);
    }
}

// single-block exclusive scan over 50000 counts -> rowptr & pos
__global__ void scan_kernel() {
    __shared__ int sm[1024];
    const int CH = (N_NODES + 1023) / 1024;   // 49
    int t = threadIdx.x;
    int base = t * CH;
    int s = 0;
    for (int i = 0; i < CH; i++) {
        int idx = base + i;
        if (idx < N_NODES) s += g_counts[idx];
    }
    sm[t] = s;
    __syncthreads();
    // Hillis-Steele inclusive scan
    for (int off = 1; off < 1024; off <<= 1) {
        int v = 0;
        if (t >= off) v = sm[t - off];
        __syncthreads();
        if (t >= off) sm[t] += v;
        __syncthreads();
    }
    int excl = (t == 0) ? 0 : sm[t - 1];
    for (int i = 0; i < CH; i++) {
        int idx = base + i;
        if (idx < N_NODES) {
            g_pos[idx]    = excl;
            g_rowptr[idx] = excl;
            excl += g_counts[idx];
        }
    }
    if (t == 0)    g_rowptr[0] = 0;
    if (t == 1023) g_rowptr[N_NODES] = excl;   // == ETOT
}

__global__ void scatter_kernel(const int* __restrict__ e0, const int* __restrict__ e1,
                               const int* __restrict__ e2,
                               const float* __restrict__ v0, const float* __restrict__ v1,
                               const float* __restrict__ v2) {
    int i = blockIdx.x * blockDim.x + threadIdx.x;
    if (i >= E_PER) return;
    {
        int r = e0[i]; int c = e0[E_PER + i]; float v = v0[i];
        int p = atomicAdd(&g_pos[r], 1);
        g_ekey[p] = (c << 2) | 0; g_ew[p] = v;
    }
    {
        int r = e1[i]; int c = e1[E_PER + i]; float v = v1[i];
        int p = atomicAdd(&g_pos[r], 1);
        g_ekey[p] = (c << 2) | 1; g_ew[p] = v;
    }
    {
        int r = e2[i]; int c = e2[E_PER + i]; float v = v2[i];
        int p = atomicAdd(&g_pos[r], 1);
        g_ekey[p] = (c << 2) | 2; g_ew[p] = v;
    }
}

// ---------------- dense: H[c] = Xin @ Ws[c], written to g_X0 ----------------
// warp per node; W (both channels, 32KB) staged in smem.
__global__ void gemm_kernel(const float* __restrict__ Xin, const float* __restrict__ W) {
    __shared__ float Wsh[2 * 64 * 64];
    int tid = threadIdx.x;
    for (int i = tid; i < 2 * 64 * 64; i += 256) Wsh[i] = W[i];
    __syncthreads();
    int warp = tid >> 5, lane = tid & 31;
    int n = blockIdx.x * 8 + warp;
    if (n >= N_NODES) return;

    float2 x = ((const float2*)Xin)[n * 32 + lane];
    float a0 = 0.f, a1 = 0.f, a2 = 0.f, a3 = 0.f;
#pragma unroll
    for (int f = 0; f < 64; f++) {
        float xf = __shfl_sync(FULL, (f & 1) ? x.y : x.x, f >> 1);
        a0 += xf * Wsh[f * 64 + lane];
        a1 += xf * Wsh[f * 64 + lane + 32];
        a2 += xf * Wsh[4096 + f * 64 + lane];
        a3 += xf * Wsh[4096 + f * 64 + lane + 32];
    }
    g_X0[n * 64 + lane]                     = a0;
    g_X0[n * 64 + lane + 32]                = a1;
    g_X0[N_NODES * 64 + n * 64 + lane]      = a2;
    g_X0[N_NODES * 64 + n * 64 + lane + 32] = a3;
}

// ---------------- SpMM: dst[c][r] = sum_e val*filt[c,t] * src[c][col], CSR by row ----
// warp per row, both channels fused. lW points at layerW[l] (6 floats, [C,T]).
__global__ void spmm_kernel(const float* __restrict__ src, float* __restrict__ dst,
                            const float* __restrict__ lW) {
    int warp = threadIdx.x >> 5, lane = threadIdx.x & 31;
    int r = blockIdx.x * 8 + warp;
    if (r >= N_NODES) return;

    // softmax over T=3, per channel (uniform across warp; L1-hot loads)
    float w00 = lW[0], w01 = lW[1], w02 = lW[2];
    float w10 = lW[3], w11 = lW[4], w12 = lW[5];
    float m0 = fmaxf(w00, fmaxf(w01, w02));
    float e00 = __expf(w00 - m0), e01 = __expf(w01 - m0), e02 = __expf(w02 - m0);
    float i0 = 1.f / (e00 + e01 + e02);
    float f00 = e00 * i0, f01 = e01 * i0, f02 = e02 * i0;
    float m1 = fmaxf(w10, fmaxf(w11, w12));
    float e10 = __expf(w10 - m1), e11 = __expf(w11 - m1), e12 = __expf(w12 - m1);
    float i1 = 1.f / (e10 + e11 + e12);
    float f10 = e10 * i1, f11 = e11 * i1, f12 = e12 * i1;

    int s = g_rowptr[r], e = g_rowptr[r + 1];
    const float2* S0 = (const float2*)src;
    const float2* S1 = (const float2*)(src + N_NODES * 64);
    float2 a0 = make_float2(0.f, 0.f);
    float2 a1 = make_float2(0.f, 0.f);

    for (int base = s; base < e; base += 32) {
        int nloc = min(32, e - base);
        int key = 0; float w = 0.f;
        if (lane < nloc) { key = g_ekey[base + lane]; w = g_ew[base + lane]; }
        for (int j = 0; j < nloc; j++) {
            int   kj = __shfl_sync(FULL, key, j);
            float wj = __shfl_sync(FULL, w, j);
            int col = kj >> 2;
            int tt  = kj & 3;
            float wf0 = wj * (tt == 0 ? f00 : (tt == 1 ? f01 : f02));
            float wf1 = wj * (tt == 0 ? f10 : (tt == 1 ? f11 : f12));
            float2 h0 = S0[col * 32 + lane];
            float2 h1 = S1[col * 32 + lane];
            a0.x += wf0 * h0.x; a0.y += wf0 * h0.y;
            a1.x += wf1 * h1.x; a1.y += wf1 * h1.y;
        }
    }
    ((float2*)dst)[r * 32 + lane] = a0;
    ((float2*)(dst + N_NODES * 64))[r * 32 + lane] = a1;
}

// ---------------- mix + linear + relu ----------------
// Hm = 0.8*relu(0.5*X0 + 0.5*H) + 0.2*X0 ; out = relu(Hm[128] @ linW[128,64] + b)
__global__ void mixlin_kernel(const float* __restrict__ Hfin,
                              const float* __restrict__ linW,
                              const float* __restrict__ linb,
                              float* __restrict__ out) {
    __shared__ float Wsh[128 * 64];
    int tid = threadIdx.x;
    for (int i = tid; i < 128 * 64; i += 256) Wsh[i] = linW[i];
    __syncthreads();
    int warp = tid >> 5, lane = tid & 31;
    int n = blockIdx.x * 8 + warp;
    if (n >= N_NODES) return;

    float hml[4];
#pragma unroll
    for (int j = 0; j < 4; j++) {
        int idx = j * 32 + lane;          // hm index: c*64 + k
        int c = idx >> 6, k = idx & 63;
        float x0v = g_X0[c * N_NODES * 64 + n * 64 + k];
        float hv  = Hfin[c * N_NODES * 64 + n * 64 + k];
        float mixv = 0.5f * x0v + 0.5f * hv;
        mixv = mixv > 0.f ? mixv : 0.f;
        hml[j] = 0.8f * mixv + 0.2f * x0v;
    }
    float acc0 = linb[lane], acc1 = linb[lane + 32];
#pragma unroll
    for (int i = 0; i < 128; i++) {
        float hv = __shfl_sync(FULL, hml[i >> 5], i & 31);
        acc0 += hv * Wsh[i * 64 + lane];
        acc1 += hv * Wsh[i * 64 + lane + 32];
    }
    out[n * 64 + lane]      = fmaxf(acc0, 0.f);
    out[n * 64 + lane + 32] = fmaxf(acc1, 0.f);
}

// ---------------- launch ----------------
extern "C" void kernel_launch(void* const* d_in, const int* in_sizes, int n_in,
                              void* d_out, int out_size) {
    const float* X    = (const float*)d_in[0];
    const float* ev0  = (const float*)d_in[1];
    const float* ev1  = (const float*)d_in[2];
    const float* ev2  = (const float*)d_in[3];
    const float* Ws0  = (const float*)d_in[4];
    const float* Ws1  = (const float*)d_in[5];
    const float* lw0  = (const float*)d_in[6];   // [2,2,3]
    const float* lw1  = (const float*)d_in[7];
    const float* lin_W0 = (const float*)d_in[8];
    const float* lin_b0 = (const float*)d_in[9];
    const float* lin_W1 = (const float*)d_in[10];
    const float* lin_b1 = (const float*)d_in[11];
    const int* ei0 = (const int*)d_in[12];
    const int* ei1 = (const int*)d_in[13];
    const int* ei2 = (const int*)d_in[14];
    float* out = (float*)d_out;

    // device-global scratch addresses (host-visible symbols)
    float* dX0;  cudaGetSymbolAddress((void**)&dX0,  g_X0);
    float* dA;   cudaGetSymbolAddress((void**)&dA,   g_A);
    float* dB;   cudaGetSymbolAddress((void**)&dB,   g_B);
    float* dXm;  cudaGetSymbolAddress((void**)&dXm,  g_Xmid);

    const int TB = 256;
    const int gridN    = (N_NODES + TB - 1) / TB;
    const int gridE    = (E_PER + TB - 1) / TB;
    const int gridWarp = (N_NODES + 7) / 8;   // warp-per-node kernels

    // CSR build (per-call, deterministic up to within-row ordering)
    zero_counts_kernel<<<gridN, TB>>>();
    hist_kernel<<<gridE, TB>>>(ei0, ei1, ei2);
    scan_kernel<<<1, 1024>>>();
    scatter_kernel<<<gridE, TB>>>(ei0, ei1, ei2, ev0, ev1, ev2);

    // ----- block 0 -----
    gemm_kernel<<<gridWarp, TB>>>(X, Ws0);               // X0 = H
    spmm_kernel<<<gridWarp, TB>>>(dX0, dA, lw0);         // layer 0
    spmm_kernel<<<gridWarp, TB>>>(dA,  dB, lw0 + 6);     // layer 1
    mixlin_kernel<<<gridWarp, TB>>>(dB, lin_W0, lin_b0, dXm);

    // ----- block 1 -----
    gemm_kernel<<<gridWarp, TB>>>(dXm, Ws1);
    spmm_kernel<<<gridWarp, TB>>>(dX0, dA, lw1);
    spmm_kernel<<<gridWarp, TB>>>(dA,  dB, lw1 + 6);
    mixlin_kernel<<<gridWarp, TB>>>(dB, lin_W1, lin_b1, out);

    (void)in_sizes; (void)n_in; (void)out_size;
}

// round 8
// speedup vs baseline: 1.0013x; 1.0013x over previous
#include <cuda_runtime.h>

#define N_NODES 50000
#define E_PER   300000
#define ETOT    900000
#define HID     64

// ---------------- scratch (__device__ globals; no allocations) ----------------
__device__ int   g_counts[N_NODES];
__device__ int   g_pos[N_NODES];
__device__ int   g_rowptr[N_NODES + 1];
__device__ int   g_ekey[ETOT];     // (col << 2) | etype
__device__ float g_ew[ETOT];       // edge value
__device__ float g_X0[2 * N_NODES * HID];   // per-channel H after GEMM (kept as X0)
__device__ float g_A [2 * N_NODES * HID];   // ping
__device__ float g_B [2 * N_NODES * HID];   // pong
__device__ float g_Xmid[N_NODES * HID];     // output of block 0

static const unsigned FULL = 0xffffffffu;

// ---------------- CSR build ----------------
__global__ void zero_counts_kernel() {
    int i = blockIdx.x * blockDim.x + threadIdx.x;
    if (i < N_NODES) g_counts[i] = 0;
}

__global__ void hist_kernel(const int* __restrict__ e0, const int* __restrict__ e1,
                            const int* __restrict__ e2) {
    int i = blockIdx.x * blockDim.x + threadIdx.x;
    if (i < E_PER) {
        atomicAdd(&g_counts[e0[i]], 1);
        atomicAdd(&g_counts[e1[i]], 1);
        atomicAdd(&g_counts[e2[i]], 1);
    }
}

// single-block exclusive scan over 50000 counts -> rowptr & pos
__global__ void scan_kernel() {
    __shared__ int sm[1024];
    const int CH = (N_NODES + 1023) / 1024;   // 49
    int t = threadIdx.x;
    int base = t * CH;
    int s = 0;
    for (int i = 0; i < CH; i++) {
        int idx = base + i;
        if (idx < N_NODES) s += g_counts[idx];
    }
    sm[t] = s;
    __syncthreads();
    // Hillis-Steele inclusive scan
    for (int off = 1; off < 1024; off <<= 1) {
        int v = 0;
        if (t >= off) v = sm[t - off];
        __syncthreads();
        if (t >= off) sm[t] += v;
        __syncthreads();
    }
    int excl = (t == 0) ? 0 : sm[t - 1];
    for (int i = 0; i < CH; i++) {
        int idx = base + i;
        if (idx < N_NODES) {
            g_pos[idx]    = excl;
            g_rowptr[idx] = excl;
            excl += g_counts[idx];
        }
    }
    if (t == 0)    g_rowptr[0] = 0;
    if (t == 1023) g_rowptr[N_NODES] = excl;   // == ETOT
}

__global__ void scatter_kernel(const int* __restrict__ e0, const int* __restrict__ e1,
                               const int* __restrict__ e2,
                               const float* __restrict__ v0, const float* __restrict__ v1,
                               const float* __restrict__ v2) {
    int i = blockIdx.x * blockDim.x + threadIdx.x;
    if (i >= E_PER) return;
    {
        int r = e0[i]; int c = e0[E_PER + i]; float v = v0[i];
        int p = atomicAdd(&g_pos[r], 1);
        g_ekey[p] = (c << 2) | 0; g_ew[p] = v;
    }
    {
        int r = e1[i]; int c = e1[E_PER + i]; float v = v1[i];
        int p = atomicAdd(&g_pos[r], 1);
        g_ekey[p] = (c << 2) | 1; g_ew[p] = v;
    }
    {
        int r = e2[i]; int c = e2[E_PER + i]; float v = v2[i];
        int p = atomicAdd(&g_pos[r], 1);
        g_ekey[p] = (c << 2) | 2; g_ew[p] = v;
    }
}

// ---------------- dense: H[c] = Xin @ Ws[c], written to g_X0 ----------------
// warp per node; W (both channels, 32KB) staged in smem.
__global__ void gemm_kernel(const float* __restrict__ Xin, const float* __restrict__ W) {
    __shared__ float Wsh[2 * 64 * 64];
    int tid = threadIdx.x;
    for (int i = tid; i < 2 * 64 * 64; i += 256) Wsh[i] = W[i];
    __syncthreads();
    int warp = tid >> 5, lane = tid & 31;
    int n = blockIdx.x * 8 + warp;
    if (n >= N_NODES) return;

    float2 x = ((const float2*)Xin)[n * 32 + lane];
    float a0 = 0.f, a1 = 0.f, a2 = 0.f, a3 = 0.f;
#pragma unroll
    for (int f = 0; f < 64; f++) {
        float xf = __shfl_sync(FULL, (f & 1) ? x.y : x.x, f >> 1);
        a0 += xf * Wsh[f * 64 + lane];
        a1 += xf * Wsh[f * 64 + lane + 32];
        a2 += xf * Wsh[4096 + f * 64 + lane];
        a3 += xf * Wsh[4096 + f * 64 + lane + 32];
    }
    g_X0[n * 64 + lane]                     = a0;
    g_X0[n * 64 + lane + 32]                = a1;
    g_X0[N_NODES * 64 + n * 64 + lane]      = a2;
    g_X0[N_NODES * 64 + n * 64 + lane + 32] = a3;
}

// ---------------- SpMM: dst[c][r] = sum_e val*filt[c,t] * src[c][col], CSR by row ----
// warp per row, both channels fused. lW points at layerW[l] (6 floats, [C,T]).
__global__ void spmm_kernel(const float* __restrict__ src, float* __restrict__ dst,
                            const float* __restrict__ lW) {
    int warp = threadIdx.x >> 5, lane = threadIdx.x & 31;
    int r = blockIdx.x * 8 + warp;
    if (r >= N_NODES) return;

    // softmax over T=3, per channel (uniform across warp; L1-hot loads)
    float w00 = lW[0], w01 = lW[1], w02 = lW[2];
    float w10 = lW[3], w11 = lW[4], w12 = lW[5];
    float m0 = fmaxf(w00, fmaxf(w01, w02));
    float e00 = __expf(w00 - m0), e01 = __expf(w01 - m0), e02 = __expf(w02 - m0);
    float i0 = 1.f / (e00 + e01 + e02);
    float f00 = e00 * i0, f01 = e01 * i0, f02 = e02 * i0;
    float m1 = fmaxf(w10, fmaxf(w11, w12));
    float e10 = __expf(w10 - m1), e11 = __expf(w11 - m1), e12 = __expf(w12 - m1);
    float i1 = 1.f / (e10 + e11 + e12);
    float f10 = e10 * i1, f11 = e11 * i1, f12 = e12 * i1;

    int s = g_rowptr[r], e = g_rowptr[r + 1];
    const float2* S0 = (const float2*)src;
    const float2* S1 = (const float2*)(src + N_NODES * 64);
    float2 a0 = make_float2(0.f, 0.f);
    float2 a1 = make_float2(0.f, 0.f);

    for (int base = s; base < e; base += 32) {
        int nloc = min(32, e - base);
        int key = 0; float w = 0.f;
        if (lane < nloc) { key = g_ekey[base + lane]; w = g_ew[base + lane]; }
        for (int j = 0; j < nloc; j++) {
            int   kj = __shfl_sync(FULL, key, j);
            float wj = __shfl_sync(FULL, w, j);
            int col = kj >> 2;
            int tt  = kj & 3;
            float wf0 = wj * (tt == 0 ? f00 : (tt == 1 ? f01 : f02));
            float wf1 = wj * (tt == 0 ? f10 : (tt == 1 ? f11 : f12));
            float2 h0 = S0[col * 32 + lane];
            float2 h1 = S1[col * 32 + lane];
            a0.x += wf0 * h0.x; a0.y += wf0 * h0.y;
            a1.x += wf1 * h1.x; a1.y += wf1 * h1.y;
        }
    }
    ((float2*)dst)[r * 32 + lane] = a0;
    ((float2*)(dst + N_NODES * 64))[r * 32 + lane] = a1;
}

// ---------------- mix + linear + relu ----------------
// Hm = 0.8*relu(0.5*X0 + 0.5*H) + 0.2*X0 ; out = relu(Hm[128] @ linW[128,64] + b)
__global__ void mixlin_kernel(const float* __restrict__ Hfin,
                              const float* __restrict__ linW,
                              const float* __restrict__ linb,
                              float* __restrict__ out) {
    __shared__ float Wsh[128 * 64];
    int tid = threadIdx.x;
    for (int i = tid; i < 128 * 64; i += 256) Wsh[i] = linW[i];
    __syncthreads();
    int warp = tid >> 5, lane = tid & 31;
    int n = blockIdx.x * 8 + warp;
    if (n >= N_NODES) return;

    float hml[4];
#pragma unroll
    for (int j = 0; j < 4; j++) {
        int idx = j * 32 + lane;          // hm index: c*64 + k
        int c = idx >> 6, k = idx & 63;
        float x0v = g_X0[c * N_NODES * 64 + n * 64 + k];
        float hv  = Hfin[c * N_NODES * 64 + n * 64 + k];
        float mixv = 0.5f * x0v + 0.5f * hv;
        mixv = mixv > 0.f ? mixv : 0.f;
        hml[j] = 0.8f * mixv + 0.2f * x0v;
    }
    float acc0 = linb[lane], acc1 = linb[lane + 32];
#pragma unroll
    for (int i = 0; i < 128; i++) {
        float hv = __shfl_sync(FULL, hml[i >> 5], i & 31);
        acc0 += hv * Wsh[i * 64 + lane];
        acc1 += hv * Wsh[i * 64 + lane + 32];
    }
    out[n * 64 + lane]      = fmaxf(acc0, 0.f);
    out[n * 64 + lane + 32] = fmaxf(acc1, 0.f);
}

// ---------------- launch ----------------
extern "C" void kernel_launch(void* const* d_in, const int* in_sizes, int n_in,
                              void* d_out, int out_size) {
    const float* X    = (const float*)d_in[0];
    const float* ev0  = (const float*)d_in[1];
    const float* ev1  = (const float*)d_in[2];
    const float* ev2  = (const float*)d_in[3];
    const float* Ws0  = (const float*)d_in[4];
    const float* Ws1  = (const float*)d_in[5];
    const float* lw0  = (const float*)d_in[6];   // [2,2,3]
    const float* lw1  = (const float*)d_in[7];
    const float* lin_W0 = (const float*)d_in[8];
    const float* lin_b0 = (const float*)d_in[9];
    const float* lin_W1 = (const float*)d_in[10];
    const float* lin_b1 = (const float*)d_in[11];
    const int* ei0 = (const int*)d_in[12];
    const int* ei1 = (const int*)d_in[13];
    const int* ei2 = (const int*)d_in[14];
    float* out = (float*)d_out;

    // device-global scratch addresses (host-visible symbols)
    float* dX0;  cudaGetSymbolAddress((void**)&dX0,  g_X0);
    float* dA;   cudaGetSymbolAddress((void**)&dA,   g_A);
    float* dB;   cudaGetSymbolAddress((void**)&dB,   g_B);
    float* dXm;  cudaGetSymbolAddress((void**)&dXm,  g_Xmid);

    const int TB = 256;
    const int gridN    = (N_NODES + TB - 1) / TB;
    const int gridE    = (E_PER + TB - 1) / TB;
    const int gridWarp = (N_NODES + 7) / 8;   // warp-per-node kernels

    // CSR build (per-call, deterministic up to within-row ordering)
    zero_counts_kernel<<<gridN, TB>>>();
    hist_kernel<<<gridE, TB>>>(ei0, ei1, ei2);
    scan_kernel<<<1, 1024>>>();
    scatter_kernel<<<gridE, TB>>>(ei0, ei1, ei2, ev0, ev1, ev2);

    // ----- block 0 -----
    gemm_kernel<<<gridWarp, TB>>>(X, Ws0);               // X0 = H
    spmm_kernel<<<gridWarp, TB>>>(dX0, dA, lw0);         // layer 0
    spmm_kernel<<<gridWarp, TB>>>(dA,  dB, lw0 + 6);     // layer 1
    mixlin_kernel<<<gridWarp, TB>>>(dB, lin_W0, lin_b0, dXm);

    // ----- block 1 -----
    gemm_kernel<<<gridWarp, TB>>>(dXm, Ws1);
    spmm_kernel<<<gridWarp, TB>>>(dX0, dA, lw1);
    spmm_kernel<<<gridWarp, TB>>>(dA,  dB, lw1 + 6);
    mixlin_kernel<<<gridWarp, TB>>>(dB, lin_W1, lin_b1, out);

    (void)in_sizes; (void)n_in; (void)out_size;
}

// round 9
// speedup vs baseline: 1.0039x; 1.0026x over previous
#include <cuda_runtime.h>

#define N_NODES 50000
#define E_PER   300000
#define ETOT    900000
#define HID     64

// ---------------- scratch (__device__ globals; no allocations) ----------------
__device__ int   g_counts[N_NODES];
__device__ int   g_pos[N_NODES];
__device__ int   g_rowptr[N_NODES + 1];
__device__ int   g_ekey[ETOT];     // (col << 2) | etype
__device__ float g_ew[ETOT];       // edge value
__device__ float g_X0[2 * N_NODES * HID];   // per-channel H after GEMM (kept as X0)
__device__ float g_A [2 * N_NODES * HID];   // ping
__device__ float g_B [2 * N_NODES * HID];   // pong
__device__ float g_Xmid[N_NODES * HID];     // output of block 0

static const unsigned FULL = 0xffffffffu;

// ---------------- CSR build ----------------
__global__ void zero_counts_kernel() {
    int i = blockIdx.x * blockDim.x + threadIdx.x;
    if (i < N_NODES) g_counts[i] = 0;
}

__global__ void hist_kernel(const int* __restrict__ e0, const int* __restrict__ e1,
                            const int* __restrict__ e2) {
    int i = blockIdx.x * blockDim.x + threadIdx.x;
    if (i < E_PER) {
        atomicAdd(&g_counts[e0[i]], 1);
        atomicAdd(&g_counts[e1[i]], 1);
        atomicAdd(&g_counts[e2[i]], 1);
    }
}

// single-block exclusive scan over 50000 counts -> rowptr & pos
__global__ void scan_kernel() {
    __shared__ int sm[1024];
    const int CH = (N_NODES + 1023) / 1024;   // 49
    int t = threadIdx.x;
    int base = t * CH;
    int s = 0;
    for (int i = 0; i < CH; i++) {
        int idx = base + i;
        if (idx < N_NODES) s += g_counts[idx];
    }
    sm[t] = s;
    __syncthreads();
    // Hillis-Steele inclusive scan
    for (int off = 1; off < 1024; off <<= 1) {
        int v = 0;
        if (t >= off) v = sm[t - off];
        __syncthreads();
        if (t >= off) sm[t] += v;
        __syncthreads();
    }
    int excl = (t == 0) ? 0 : sm[t - 1];
    for (int i = 0; i < CH; i++) {
        int idx = base + i;
        if (idx < N_NODES) {
            g_pos[idx]    = excl;
            g_rowptr[idx] = excl;
            excl += g_counts[idx];
        }
    }
    if (t == 0)    g_rowptr[0] = 0;
    if (t == 1023) g_rowptr[N_NODES] = excl;   // == ETOT
}

__global__ void scatter_kernel(const int* __restrict__ e0, const int* __restrict__ e1,
                               const int* __restrict__ e2,
                               const float* __restrict__ v0, const float* __restrict__ v1,
                               const float* __restrict__ v2) {
    int i = blockIdx.x * blockDim.x + threadIdx.x;
    if (i >= E_PER) return;
    {
        int r = e0[i]; int c = e0[E_PER + i]; float v = v0[i];
        int p = atomicAdd(&g_pos[r], 1);
        g_ekey[p] = (c << 2) | 0; g_ew[p] = v;
    }
    {
        int r = e1[i]; int c = e1[E_PER + i]; float v = v1[i];
        int p = atomicAdd(&g_pos[r], 1);
        g_ekey[p] = (c << 2) | 1; g_ew[p] = v;
    }
    {
        int r = e2[i]; int c = e2[E_PER + i]; float v = v2[i];
        int p = atomicAdd(&g_pos[r], 1);
        g_ekey[p] = (c << 2) | 2; g_ew[p] = v;
    }
}

// ---------------- dense: H[c] = Xin @ Ws[c], written to g_X0 ----------------
// warp per node; W (both channels, 32KB) staged in smem.
__global__ void gemm_kernel(const float* __restrict__ Xin, const float* __restrict__ W) {
    __shared__ float Wsh[2 * 64 * 64];
    int tid = threadIdx.x;
    for (int i = tid; i < 2 * 64 * 64; i += 256) Wsh[i] = W[i];
    __syncthreads();
    int warp = tid >> 5, lane = tid & 31;
    int n = blockIdx.x * 8 + warp;
    if (n >= N_NODES) return;

    float2 x = ((const float2*)Xin)[n * 32 + lane];
    float a0 = 0.f, a1 = 0.f, a2 = 0.f, a3 = 0.f;
#pragma unroll
    for (int f = 0; f < 64; f++) {
        float xf = __shfl_sync(FULL, (f & 1) ? x.y : x.x, f >> 1);
        a0 += xf * Wsh[f * 64 + lane];
        a1 += xf * Wsh[f * 64 + lane + 32];
        a2 += xf * Wsh[4096 + f * 64 + lane];
        a3 += xf * Wsh[4096 + f * 64 + lane + 32];
    }
    g_X0[n * 64 + lane]                     = a0;
    g_X0[n * 64 + lane + 32]                = a1;
    g_X0[N_NODES * 64 + n * 64 + lane]      = a2;
    g_X0[N_NODES * 64 + n * 64 + lane + 32] = a3;
}

// ---------------- SpMM: dst[c][r] = sum_e val*filt[c,t] * src[c][col], CSR by row ----
// warp per row, both channels fused. lW points at layerW[l] (6 floats, [C,T]).
__global__ void spmm_kernel(const float* __restrict__ src, float* __restrict__ dst,
                            const float* __restrict__ lW) {
    int warp = threadIdx.x >> 5, lane = threadIdx.x & 31;
    int r = blockIdx.x * 8 + warp;
    if (r >= N_NODES) return;

    // softmax over T=3, per channel (uniform across warp; L1-hot loads)
    float w00 = lW[0], w01 = lW[1], w02 = lW[2];
    float w10 = lW[3], w11 = lW[4], w12 = lW[5];
    float m0 = fmaxf(w00, fmaxf(w01, w02));
    float e00 = __expf(w00 - m0), e01 = __expf(w01 - m0), e02 = __expf(w02 - m0);
    float i0 = 1.f / (e00 + e01 + e02);
    float f00 = e00 * i0, f01 = e01 * i0, f02 = e02 * i0;
    float m1 = fmaxf(w10, fmaxf(w11, w12));
    float e10 = __expf(w10 - m1), e11 = __expf(w11 - m1), e12 = __expf(w12 - m1);
    float i1 = 1.f / (e10 + e11 + e12);
    float f10 = e10 * i1, f11 = e11 * i1, f12 = e12 * i1;

    int s = g_rowptr[r], e = g_rowptr[r + 1];
    const float2* S0 = (const float2*)src;
    const float2* S1 = (const float2*)(src + N_NODES * 64);
    float2 a0 = make_float2(0.f, 0.f);
    float2 a1 = make_float2(0.f, 0.f);

    for (int base = s; base < e; base += 32) {
        int nloc = min(32, e - base);
        int key = 0; float w = 0.f;
        if (lane < nloc) { key = g_ekey[base + lane]; w = g_ew[base + lane]; }
        for (int j = 0; j < nloc; j++) {
            int   kj = __shfl_sync(FULL, key, j);
            float wj = __shfl_sync(FULL, w, j);
            int col = kj >> 2;
            int tt  = kj & 3;
            float wf0 = wj * (tt == 0 ? f00 : (tt == 1 ? f01 : f02));
            float wf1 = wj * (tt == 0 ? f10 : (tt == 1 ? f11 : f12));
            float2 h0 = S0[col * 32 + lane];
            float2 h1 = S1[col * 32 + lane];
            a0.x += wf0 * h0.x; a0.y += wf0 * h0.y;
            a1.x += wf1 * h1.x; a1.y += wf1 * h1.y;
        }
    }
    ((float2*)dst)[r * 32 + lane] = a0;
    ((float2*)(dst + N_NODES * 64))[r * 32 + lane] = a1;
}

// ---------------- mix + linear + relu ----------------
// Hm = 0.8*relu(0.5*X0 + 0.5*H) + 0.2*X0 ; out = relu(Hm[128] @ linW[128,64] + b)
__global__ void mixlin_kernel(const float* __restrict__ Hfin,
                              const float* __restrict__ linW,
                              const float* __restrict__ linb,
                              float* __restrict__ out) {
    __shared__ float Wsh[128 * 64];
    int tid = threadIdx.x;
    for (int i = tid; i < 128 * 64; i += 256) Wsh[i] = linW[i];
    __syncthreads();
    int warp = tid >> 5, lane = tid & 31;
    int n = blockIdx.x * 8 + warp;
    if (n >= N_NODES) return;

    float hml[4];
#pragma unroll
    for (int j = 0; j < 4; j++) {
        int idx = j * 32 + lane;          // hm index: c*64 + k
        int c = idx >> 6, k = idx & 63;
        float x0v = g_X0[c * N_NODES * 64 + n * 64 + k];
        float hv  = Hfin[c * N_NODES * 64 + n * 64 + k];
        float mixv = 0.5f * x0v + 0.5f * hv;
        mixv = mixv > 0.f ? mixv : 0.f;
        hml[j] = 0.8f * mixv + 0.2f * x0v;
    }
    float acc0 = linb[lane], acc1 = linb[lane + 32];
#pragma unroll
    for (int i = 0; i < 128; i++) {
        float hv = __shfl_sync(FULL, hml[i >> 5], i & 31);
        acc0 += hv * Wsh[i * 64 + lane];
        acc1 += hv * Wsh[i * 64 + lane + 32];
    }
    out[n * 64 + lane]      = fmaxf(acc0, 0.f);
    out[n * 64 + lane + 32] = fmaxf(acc1, 0.f);
}

// ---------------- launch ----------------
extern "C" void kernel_launch(void* const* d_in, const int* in_sizes, int n_in,
                              void* d_out, int out_size) {
    const float* X    = (const float*)d_in[0];
    const float* ev0  = (const float*)d_in[1];
    const float* ev1  = (const float*)d_in[2];
    const float* ev2  = (const float*)d_in[3];
    const float* Ws0  = (const float*)d_in[4];
    const float* Ws1  = (const float*)d_in[5];
    const float* lw0  = (const float*)d_in[6];   // [2,2,3]
    const float* lw1  = (const float*)d_in[7];
    const float* lin_W0 = (const float*)d_in[8];
    const float* lin_b0 = (const float*)d_in[9];
    const float* lin_W1 = (const float*)d_in[10];
    const float* lin_b1 = (const float*)d_in[11];
    const int* ei0 = (const int*)d_in[12];
    const int* ei1 = (const int*)d_in[13];
    const int* ei2 = (const int*)d_in[14];
    float* out = (float*)d_out;

    // device-global scratch addresses (host-visible symbols)
    float* dX0;  cudaGetSymbolAddress((void**)&dX0,  g_X0);
    float* dA;   cudaGetSymbolAddress((void**)&dA,   g_A);
    float* dB;   cudaGetSymbolAddress((void**)&dB,   g_B);
    float* dXm;  cudaGetSymbolAddress((void**)&dXm,  g_Xmid);

    const int TB = 256;
    const int gridN    = (N_NODES + TB - 1) / TB;
    const int gridE    = (E_PER + TB - 1) / TB;
    const int gridWarp = (N_NODES + 7) / 8;   // warp-per-node kernels

    // CSR build (per-call, deterministic up to within-row ordering)
    zero_counts_kernel<<<gridN, TB>>>();
    hist_kernel<<<gridE, TB>>>(ei0, ei1, ei2);
    scan_kernel<<<1, 1024>>>();
    scatter_kernel<<<gridE, TB>>>(ei0, ei1, ei2, ev0, ev1, ev2);

    // ----- block 0 -----
    gemm_kernel<<<gridWarp, TB>>>(X, Ws0);               // X0 = H
    spmm_kernel<<<gridWarp, TB>>>(dX0, dA, lw0);         // layer 0
    spmm_kernel<<<gridWarp, TB>>>(dA,  dB, lw0 + 6);     // layer 1
    mixlin_kernel<<<gridWarp, TB>>>(dB, lin_W0, lin_b0, dXm);

    // ----- block 1 -----
    gemm_kernel<<<gridWarp, TB>>>(dXm, Ws1);
    spmm_kernel<<<gridWarp, TB>>>(dX0, dA, lw1);
    spmm_kernel<<<gridWarp, TB>>>(dA,  dB, lw1 + 6);
    mixlin_kernel<<<gridWarp, TB>>>(dB, lin_W1, lin_b1, out);

    (void)in_sizes; (void)n_in; (void)out_size;
}